// round 13
// baseline (speedup 1.0000x reference)
#include <cuda_runtime.h>
#include <cuda_bf16.h>

#define TT    2048
#define BB    32
#define DD    512
#define HH    512
#define BTR   (BB * TT)          // 65536
#define NCTA  128
#define NGRP  4                  // batch groups (8 batches each)
#define CPG   32                 // CTAs per group (16 j each)

// ---------------- device scratch ----------------
__device__ float g_proj[(size_t)BTR * DD];               // 128 MB
__device__ float g_pre[(size_t)TT * HH * BB * 4];        // 512 MB  [t][j][b][gate]
__device__ float g_wcat[DD * 4 * HH];                    // 4 MB    [k][c], c = j*4+g
__device__ float g_bcat[4 * HH];
// h exchange per group: pairs {h_bits, gen}, [k512][b8], double-buffered
__device__ __align__(16) uint2 g_hx[2][NGRP][HH * 8];    // 256 KB

// ---------------- helpers ----------------
__device__ __forceinline__ unsigned long long ffma2(unsigned long long a,
                                                    unsigned long long b,
                                                    unsigned long long c) {
    unsigned long long d;
    asm("fma.rn.f32x2 %0, %1, %2, %3;" : "=l"(d) : "l"(a), "l"(b), "l"(c));
    return d;
}
__device__ __forceinline__ unsigned long long pack2(float x) {
    unsigned long long d;
    asm("mov.b64 %0, {%1, %1};" : "=l"(d) : "f"(x));
    return d;
}
__device__ __forceinline__ float2 unpack2(unsigned long long v) {
    float2 r;
    asm("mov.b64 {%0, %1}, %2;" : "=f"(r.x), "=f"(r.y) : "l"(v));
    return r;
}
// size-matched 8B atomic pair ops (same size as publish -> single-copy atomic)
__device__ __forceinline__ unsigned long long ldpair(const uint2* p) {
    unsigned long long v;
    asm volatile("ld.relaxed.gpu.b64 %0, [%1];" : "=l"(v) : "l"(p) : "memory");
    return v;
}
__device__ __forceinline__ void stpair(uint2* p, unsigned long long v) {
    asm volatile("st.relaxed.gpu.b64 [%0], %1;" :: "l"(p), "l"(v) : "memory");
}

__device__ __forceinline__ float sig_(float x) {
    return __fdividef(1.f, 1.f + __expf(-x));
}
__device__ __forceinline__ float tanh_(float x) {
    return 1.f - __fdividef(2.f, __expf(2.f * x) + 1.f);
}

// ---------------- pack weights + init state ----------------
__global__ void pack_kernel(const float* __restrict__ Wf, const float* __restrict__ Wi,
                            const float* __restrict__ Wc, const float* __restrict__ Wo,
                            const float* __restrict__ bf, const float* __restrict__ bi,
                            const float* __restrict__ bc, const float* __restrict__ bo) {
    int idx = blockIdx.x * 256 + threadIdx.x;
    if (idx < DD * 4 * HH) {
        int k = idx >> 11;         // input-half row of W_*
        int c = idx & 2047;        // c = j*4+g
        int j = c >> 2, g = c & 3;
        const float* W = (g == 0) ? Wf : (g == 1) ? Wi : (g == 2) ? Wc : Wo;
        g_wcat[idx] = W[(size_t)k * HH + j];
    }
    if (idx < 4 * HH) {
        int j = idx >> 2, g = idx & 3;
        const float* bv = (g == 0) ? bf : (g == 1) ? bi : (g == 2) ? bc : bo;
        g_bcat[idx] = bv[j];
    }
    // init both buffers of all groups to {h=0.0, gen=0}
    if (idx < 2 * NGRP * HH * 8) ((uint2*)g_hx)[idx] = make_uint2(0u, 0u);
}

// ---------------- fp32 SIMT GEMM, f32x2 accumulation (unchanged, proven) ----------------
__global__ __launch_bounds__(256, 2) void gemm_kernel(
    int stage, const float* __restrict__ Aext, const float* __restrict__ Bext,
    const float* __restrict__ biasext) {
    __shared__ __align__(16) float As[16][132];
    __shared__ __align__(16) float Bs[16][128];

    const float* A    = (stage == 0) ? Aext    : g_proj;
    const float* B    = (stage == 0) ? Bext    : g_wcat;
    const float* bias = (stage == 0) ? biasext : g_bcat;
    float* out = (stage == 0) ? g_proj : g_pre;
    const int ldb = (stage == 0) ? 512 : 2048;

    const int tid = threadIdx.x;
    const int m0 = blockIdx.y * 128;
    const int n0 = blockIdx.x * 128;
    const int tm = tid >> 4, tn = tid & 15;

    unsigned long long acc[4][8];
    #pragma unroll
    for (int p = 0; p < 4; p++)
        #pragma unroll
        for (int n = 0; n < 8; n++) acc[p][n] = 0ull;

    for (int k0 = 0; k0 < 512; k0 += 16) {
        #pragma unroll
        for (int i = 0; i < 2; i++) {
            int idx = tid + i * 256;
            int row = idx >> 2, c4 = idx & 3;
            float4 v = *(const float4*)(A + (size_t)(m0 + row) * 512 + k0 + c4 * 4);
            As[c4 * 4 + 0][row] = v.x;
            As[c4 * 4 + 1][row] = v.y;
            As[c4 * 4 + 2][row] = v.z;
            As[c4 * 4 + 3][row] = v.w;
        }
        #pragma unroll
        for (int i = 0; i < 2; i++) {
            int idx = tid + i * 256;
            int row = idx >> 5, c4 = idx & 31;
            *(float4*)&Bs[row][c4 * 4] =
                *(const float4*)(B + (size_t)(k0 + row) * ldb + n0 + c4 * 4);
        }
        __syncthreads();
        #pragma unroll
        for (int kk = 0; kk < 16; kk++) {
            ulonglong2 aA = *(const ulonglong2*)&As[kk][tm * 8];
            ulonglong2 aB = *(const ulonglong2*)&As[kk][tm * 8 + 4];
            float4 b0 = *(const float4*)&Bs[kk][tn * 8];
            float4 b1 = *(const float4*)&Bs[kk][tn * 8 + 4];
            unsigned long long bd[8];
            bd[0] = pack2(b0.x); bd[1] = pack2(b0.y); bd[2] = pack2(b0.z); bd[3] = pack2(b0.w);
            bd[4] = pack2(b1.x); bd[5] = pack2(b1.y); bd[6] = pack2(b1.z); bd[7] = pack2(b1.w);
            #pragma unroll
            for (int n = 0; n < 8; n++) {
                acc[0][n] = ffma2(aA.x, bd[n], acc[0][n]);
                acc[1][n] = ffma2(aA.y, bd[n], acc[1][n]);
                acc[2][n] = ffma2(aB.x, bd[n], acc[2][n]);
                acc[3][n] = ffma2(aB.y, bd[n], acc[3][n]);
            }
        }
        __syncthreads();
    }

    float4 bs0 = *(const float4*)&bias[n0 + tn * 8];
    float4 bs1 = *(const float4*)&bias[n0 + tn * 8 + 4];
    float bv[8] = {bs0.x, bs0.y, bs0.z, bs0.w, bs1.x, bs1.y, bs1.z, bs1.w};

    #pragma unroll
    for (int p = 0; p < 4; p++) {
        int r0 = m0 + tm * 8 + 2 * p;
        #pragma unroll
        for (int jj = 0; jj < 2; jj++) {
            float2 u0 = unpack2(acc[p][jj * 4 + 0]);
            float2 u1 = unpack2(acc[p][jj * 4 + 1]);
            float2 u2 = unpack2(acc[p][jj * 4 + 2]);
            float2 u3 = unpack2(acc[p][jj * 4 + 3]);
            float4 lo4, hi4;
            lo4.x = u0.x + bv[jj * 4 + 0]; hi4.x = u0.y + bv[jj * 4 + 0];
            lo4.y = u1.x + bv[jj * 4 + 1]; hi4.y = u1.y + bv[jj * 4 + 1];
            lo4.z = u2.x + bv[jj * 4 + 2]; hi4.z = u2.y + bv[jj * 4 + 2];
            lo4.w = u3.x + bv[jj * 4 + 3]; hi4.w = u3.y + bv[jj * 4 + 3];
            if (stage == 0) {
                lo4.x = tanh_(lo4.x); lo4.y = tanh_(lo4.y);
                lo4.z = tanh_(lo4.z); lo4.w = tanh_(lo4.w);
                hi4.x = tanh_(hi4.x); hi4.y = tanh_(hi4.y);
                hi4.z = tanh_(hi4.z); hi4.w = tanh_(hi4.w);
                int c0 = n0 + tn * 8 + jj * 4;
                *(float4*)(out + (size_t)r0 * 512 + c0)       = lo4;
                *(float4*)(out + (size_t)(r0 + 1) * 512 + c0) = hi4;
            } else {
                int b  = r0 >> 11;
                int t0 = r0 & 2047;
                int jglob = ((n0 + tn * 8) >> 2) + jj;
                *(float4*)(out + (((size_t)t0 * 512 + jglob) * 32 + b) * 4)       = lo4;
                *(float4*)(out + (((size_t)(t0 + 1) * 512 + jglob) * 32 + b) * 4) = hi4;
            }
        }
    }
}

// ---------------- persistent scan: 4 batch-groups x 32 CTAs ----------------
// CTA (grp, c): batches b0=grp*8..+7, hidden cols j0=c*16..+15, all 4 gates.
// 256 threads, 8 warps; warp w: k in [w*64, w*64+64); lane: b=lane&7, jq=lane>>3.
// SMEM map (bytes):
//   w_s  [512k][4jq][4m] uint4 {f,i,c,o}, jq stride 80 (bank-staggered), k stride 320
//        : 163840 @ 0
//   h_s  [512k][8b] f32                  : 16384  @ 163840
//   part [2][8w][16j*8b] uint4           : 32768  @ 180224
//   c_s  128 f32                         : 512    @ 212992
#define W_OFF     0
#define H_OFF     163840
#define PART_OFF  180224
#define C_OFF     212992
#define SCAN_SMEM 213504

__global__ __launch_bounds__(256, 1) void lstm_scan_kernel(
    const float* __restrict__ Wf, const float* __restrict__ Wi,
    const float* __restrict__ Wc, const float* __restrict__ Wo,
    float* __restrict__ out) {
    extern __shared__ __align__(16) char smraw[];
    uint4* part4 = (uint4*)(smraw + PART_OFF);
    float* c_s   = (float*)(smraw + C_OFF);

    const int tid  = threadIdx.x;
    const int lane = tid & 31;
    const int wrp  = tid >> 5;
    const int grp  = blockIdx.x >> 5;          // 0..3
    const int cix  = blockIdx.x & 31;          // 0..31
    const int j0   = cix * 16;
    const int b0   = grp * 8;

    // fill weight cache: rows 512..1023 of W_*, cols j0..j0+15, staggered layout
    for (int idx = tid; idx < 512 * 16; idx += 256) {
        int j = idx & 15, k = idx >> 4;
        size_t off = (size_t)(512 + k) * HH + (j0 + j);
        uint4 w;
        w.x = __float_as_uint(Wf[off]); w.y = __float_as_uint(Wi[off]);
        w.z = __float_as_uint(Wc[off]); w.w = __float_as_uint(Wo[off]);
        *(uint4*)(smraw + W_OFF + k * 320 + (j >> 2) * 80 + (j & 3) * 16) = w;
    }
    if (tid < 128) c_s[tid] = 0.f;
    __syncthreads();

    const char* wbase = smraw + W_OFF + (wrp * 64) * 320 + (lane >> 3) * 80;
    const char* hbase = smraw + H_OFF + (wrp * 64) * 32 + (lane & 7) * 4;
    unsigned*   hstg  = (unsigned*)(smraw + H_OFF) + wrp * 512;   // warp-private slice

    for (int t = 0; t < TT; t++) {
        const int pbuf = t & 1;
        const unsigned egen = (unsigned)t;        // expect gen t in buf[t&1]
        const unsigned pgen = (unsigned)(t + 1);  // publish gen t+1 to buf[(t+1)&1]

        // prefetch this step's input-half pre-activations
        float4 pre4 = make_float4(0.f, 0.f, 0.f, 0.f);
        if (tid < 128) {
            int rj = tid >> 3, rb = tid & 7;
            pre4 = *(const float4*)(g_pre + (((size_t)t * 512 + j0 + rj) * 32 + b0 + rb) * 4);
        }

        // poll-load warp's h slice: 512 pairs, 16 per lane, batch-issued then checked
        {
            const uint2* hx = &g_hx[t & 1][grp][wrp * 512];
            unsigned long long vals[16];
            #pragma unroll
            for (int i = 0; i < 16; i++) vals[i] = ldpair(hx + i * 32 + lane);
            #pragma unroll
            for (int i = 0; i < 16; i++) {
                while ((unsigned)(vals[i] >> 32) != egen)
                    vals[i] = ldpair(hx + i * 32 + lane);
                hstg[i * 32 + lane] = (unsigned)vals[i];     // value word -> smem
            }
        }
        __syncwarp();

        // compute: 64 k-iters; per k: 1 h LDS (broadcast) + 4 LDS.128 + 8 FFMA2
        unsigned long long afi0 = 0, afi1 = 0, afi2 = 0, afi3 = 0;
        unsigned long long aco0 = 0, aco1 = 0, aco2 = 0, aco3 = 0;
        #pragma unroll 8
        for (int kk = 0; kk < 64; kk++) {
            unsigned long long hv = pack2(*(const float*)(hbase + kk * 32));
            ulonglong2 w0 = *(const ulonglong2*)(wbase + kk * 320);
            ulonglong2 w1 = *(const ulonglong2*)(wbase + kk * 320 + 16);
            ulonglong2 w2 = *(const ulonglong2*)(wbase + kk * 320 + 32);
            ulonglong2 w3 = *(const ulonglong2*)(wbase + kk * 320 + 48);
            afi0 = ffma2(hv, w0.x, afi0); aco0 = ffma2(hv, w0.y, aco0);
            afi1 = ffma2(hv, w1.x, afi1); aco1 = ffma2(hv, w1.y, aco1);
            afi2 = ffma2(hv, w2.x, afi2); aco2 = ffma2(hv, w2.y, aco2);
            afi3 = ffma2(hv, w3.x, afi3); aco3 = ffma2(hv, w3.y, aco3);
        }
        {
            uint4* pp = part4 + pbuf * 1024 + wrp * 128 + (lane >> 3) * 32 + (lane & 7);
            float2 a, b2;
            a = unpack2(afi0); b2 = unpack2(aco0);
            pp[0]  = make_uint4(__float_as_uint(a.x), __float_as_uint(a.y),
                                __float_as_uint(b2.x), __float_as_uint(b2.y));
            a = unpack2(afi1); b2 = unpack2(aco1);
            pp[8]  = make_uint4(__float_as_uint(a.x), __float_as_uint(a.y),
                                __float_as_uint(b2.x), __float_as_uint(b2.y));
            a = unpack2(afi2); b2 = unpack2(aco2);
            pp[16] = make_uint4(__float_as_uint(a.x), __float_as_uint(a.y),
                                __float_as_uint(b2.x), __float_as_uint(b2.y));
            a = unpack2(afi3); b2 = unpack2(aco3);
            pp[24] = make_uint4(__float_as_uint(a.x), __float_as_uint(a.y),
                                __float_as_uint(b2.x), __float_as_uint(b2.y));
        }
        __syncthreads();   // only per-step CTA sync

        if (tid < 128) {
            int rj = tid >> 3, rb = tid & 7;
            float rf = 0.f, ri = 0.f, rc = 0.f, ro = 0.f;
            #pragma unroll
            for (int w = 0; w < 8; w++) {
                uint4 v = part4[pbuf * 1024 + w * 128 + tid];
                rf += __uint_as_float(v.x);
                ri += __uint_as_float(v.y);
                rc += __uint_as_float(v.z);
                ro += __uint_as_float(v.w);
            }
            float f  = sig_(pre4.x + rf);
            float ii = sig_(pre4.y + ri);
            float cg = tanh_(pre4.z + rc);
            float o  = sig_(pre4.w + ro);
            float cn = f * c_s[tid] + ii * cg;
            c_s[tid] = cn;
            float h = o * tanh_(cn);
            unsigned long long pub =
                ((unsigned long long)pgen << 32) | (unsigned long long)__float_as_uint(h);
            stpair(&g_hx[(t + 1) & 1][grp][(j0 + rj) * 8 + rb], pub);
            out[((size_t)(b0 + rb) * TT + t) * HH + j0 + rj] = h;
        }
        // no grid barrier: gen polls provide all inter-CTA ordering (span = 32)
    }
}

extern "C" void kernel_launch(void* const* d_in, const int* in_sizes, int n_in,
                              void* d_out, int out_size) {
    const float* X   = (const float*)d_in[0];
    const float* W_p = (const float*)d_in[1];
    const float* b_p = (const float*)d_in[2];
    const float* W_f = (const float*)d_in[3];
    const float* b_f = (const float*)d_in[4];
    const float* W_i = (const float*)d_in[5];
    const float* b_i = (const float*)d_in[6];
    const float* W_c = (const float*)d_in[7];
    const float* b_c = (const float*)d_in[8];
    const float* W_o = (const float*)d_in[9];
    const float* b_o = (const float*)d_in[10];
    float* out = (float*)d_out;

    cudaFuncSetAttribute(lstm_scan_kernel,
                         cudaFuncAttributeMaxDynamicSharedMemorySize, SCAN_SMEM);

    pack_kernel<<<4096, 256>>>(W_f, W_i, W_c, W_o, b_f, b_i, b_c, b_o);
    gemm_kernel<<<dim3(4, 512), 256>>>(0, X, W_p, b_p);
    gemm_kernel<<<dim3(16, 512), 256>>>(1, nullptr, nullptr, nullptr);
    lstm_scan_kernel<<<NCTA, 256, SCAN_SMEM>>>(W_f, W_i, W_c, W_o, out);
}

// round 14
// speedup vs baseline: 1.3671x; 1.3671x over previous
#include <cuda_runtime.h>
#include <cuda_bf16.h>

#define TT    2048
#define BB    32
#define DD    512
#define HH    512
#define BTR   (BB * TT)          // 65536
#define NCTA  128
#define NGRP  4                  // batch groups (8 batches each)
#define CPG   32                 // CTAs per group (16 j each)

// ---------------- device scratch ----------------
__device__ float g_proj[(size_t)BTR * DD];               // 128 MB
__device__ float g_pre[(size_t)TT * HH * BB * 4];        // 512 MB  [t][j][b][gate]
__device__ float g_wcat[DD * 4 * HH];                    // 4 MB    [k][c], c = j*4+g
__device__ float g_bcat[4 * HH];
// h exchange per group: plain floats [j512][b8], double-buffered
__device__ __align__(16) float g_hgrp[2][NGRP][HH * 8];  // 128 KB
// one flag per producer CTA, 128B-strided: flag = last published generation
__device__ unsigned int g_flags[NGRP * CPG * 32];        // 16 KB

// ---------------- helpers ----------------
__device__ __forceinline__ unsigned long long ffma2(unsigned long long a,
                                                    unsigned long long b,
                                                    unsigned long long c) {
    unsigned long long d;
    asm("fma.rn.f32x2 %0, %1, %2, %3;" : "=l"(d) : "l"(a), "l"(b), "l"(c));
    return d;
}
__device__ __forceinline__ unsigned long long pack2(float x) {
    unsigned long long d;
    asm("mov.b64 %0, {%1, %1};" : "=l"(d) : "f"(x));
    return d;
}
__device__ __forceinline__ float2 unpack2(unsigned long long v) {
    float2 r;
    asm("mov.b64 {%0, %1}, %2;" : "=f"(r.x), "=f"(r.y) : "l"(v));
    return r;
}
__device__ __forceinline__ float4 ldcv4(const float* p) {
    float4 v;
    asm volatile("ld.global.cv.v4.f32 {%0,%1,%2,%3}, [%4];"
                 : "=f"(v.x), "=f"(v.y), "=f"(v.z), "=f"(v.w) : "l"(p));
    return v;
}
__device__ __forceinline__ unsigned ldacq(const unsigned* p) {
    unsigned v;
    asm volatile("ld.acquire.gpu.u32 %0, [%1];" : "=r"(v) : "l"(p) : "memory");
    return v;
}

__device__ __forceinline__ float sig_(float x) {
    return __fdividef(1.f, 1.f + __expf(-x));
}
__device__ __forceinline__ float tanh_(float x) {
    return 1.f - __fdividef(2.f, __expf(2.f * x) + 1.f);
}

// ---------------- pack weights + init state ----------------
__global__ void pack_kernel(const float* __restrict__ Wf, const float* __restrict__ Wi,
                            const float* __restrict__ Wc, const float* __restrict__ Wo,
                            const float* __restrict__ bf, const float* __restrict__ bi,
                            const float* __restrict__ bc, const float* __restrict__ bo) {
    int idx = blockIdx.x * 256 + threadIdx.x;
    if (idx < DD * 4 * HH) {
        int k = idx >> 11;         // input-half row of W_*
        int c = idx & 2047;        // c = j*4+g
        int j = c >> 2, g = c & 3;
        const float* W = (g == 0) ? Wf : (g == 1) ? Wi : (g == 2) ? Wc : Wo;
        g_wcat[idx] = W[(size_t)k * HH + j];
    }
    if (idx < 4 * HH) {
        int j = idx >> 2, g = idx & 3;
        const float* bv = (g == 0) ? bf : (g == 1) ? bi : (g == 2) ? bc : bo;
        g_bcat[idx] = bv[j];
    }
    if (idx < 2 * NGRP * HH * 8) ((float*)g_hgrp)[idx] = 0.f;   // h0 = 0
    if (idx < NGRP * CPG * 32) g_flags[idx] = 0u;               // gen 0 published
}

// ---------------- fp32 SIMT GEMM, f32x2 accumulation (unchanged, proven) ----------------
__global__ __launch_bounds__(256, 2) void gemm_kernel(
    int stage, const float* __restrict__ Aext, const float* __restrict__ Bext,
    const float* __restrict__ biasext) {
    __shared__ __align__(16) float As[16][132];
    __shared__ __align__(16) float Bs[16][128];

    const float* A    = (stage == 0) ? Aext    : g_proj;
    const float* B    = (stage == 0) ? Bext    : g_wcat;
    const float* bias = (stage == 0) ? biasext : g_bcat;
    float* out = (stage == 0) ? g_proj : g_pre;
    const int ldb = (stage == 0) ? 512 : 2048;

    const int tid = threadIdx.x;
    const int m0 = blockIdx.y * 128;
    const int n0 = blockIdx.x * 128;
    const int tm = tid >> 4, tn = tid & 15;

    unsigned long long acc[4][8];
    #pragma unroll
    for (int p = 0; p < 4; p++)
        #pragma unroll
        for (int n = 0; n < 8; n++) acc[p][n] = 0ull;

    for (int k0 = 0; k0 < 512; k0 += 16) {
        #pragma unroll
        for (int i = 0; i < 2; i++) {
            int idx = tid + i * 256;
            int row = idx >> 2, c4 = idx & 3;
            float4 v = *(const float4*)(A + (size_t)(m0 + row) * 512 + k0 + c4 * 4);
            As[c4 * 4 + 0][row] = v.x;
            As[c4 * 4 + 1][row] = v.y;
            As[c4 * 4 + 2][row] = v.z;
            As[c4 * 4 + 3][row] = v.w;
        }
        #pragma unroll
        for (int i = 0; i < 2; i++) {
            int idx = tid + i * 256;
            int row = idx >> 5, c4 = idx & 31;
            *(float4*)&Bs[row][c4 * 4] =
                *(const float4*)(B + (size_t)(k0 + row) * ldb + n0 + c4 * 4);
        }
        __syncthreads();
        #pragma unroll
        for (int kk = 0; kk < 16; kk++) {
            ulonglong2 aA = *(const ulonglong2*)&As[kk][tm * 8];
            ulonglong2 aB = *(const ulonglong2*)&As[kk][tm * 8 + 4];
            float4 b0 = *(const float4*)&Bs[kk][tn * 8];
            float4 b1 = *(const float4*)&Bs[kk][tn * 8 + 4];
            unsigned long long bd[8];
            bd[0] = pack2(b0.x); bd[1] = pack2(b0.y); bd[2] = pack2(b0.z); bd[3] = pack2(b0.w);
            bd[4] = pack2(b1.x); bd[5] = pack2(b1.y); bd[6] = pack2(b1.z); bd[7] = pack2(b1.w);
            #pragma unroll
            for (int n = 0; n < 8; n++) {
                acc[0][n] = ffma2(aA.x, bd[n], acc[0][n]);
                acc[1][n] = ffma2(aA.y, bd[n], acc[1][n]);
                acc[2][n] = ffma2(aB.x, bd[n], acc[2][n]);
                acc[3][n] = ffma2(aB.y, bd[n], acc[3][n]);
            }
        }
        __syncthreads();
    }

    float4 bs0 = *(const float4*)&bias[n0 + tn * 8];
    float4 bs1 = *(const float4*)&bias[n0 + tn * 8 + 4];
    float bv[8] = {bs0.x, bs0.y, bs0.z, bs0.w, bs1.x, bs1.y, bs1.z, bs1.w};

    #pragma unroll
    for (int p = 0; p < 4; p++) {
        int r0 = m0 + tm * 8 + 2 * p;
        #pragma unroll
        for (int jj = 0; jj < 2; jj++) {
            float2 u0 = unpack2(acc[p][jj * 4 + 0]);
            float2 u1 = unpack2(acc[p][jj * 4 + 1]);
            float2 u2 = unpack2(acc[p][jj * 4 + 2]);
            float2 u3 = unpack2(acc[p][jj * 4 + 3]);
            float4 lo4, hi4;
            lo4.x = u0.x + bv[jj * 4 + 0]; hi4.x = u0.y + bv[jj * 4 + 0];
            lo4.y = u1.x + bv[jj * 4 + 1]; hi4.y = u1.y + bv[jj * 4 + 1];
            lo4.z = u2.x + bv[jj * 4 + 2]; hi4.z = u2.y + bv[jj * 4 + 2];
            lo4.w = u3.x + bv[jj * 4 + 3]; hi4.w = u3.y + bv[jj * 4 + 3];
            if (stage == 0) {
                lo4.x = tanh_(lo4.x); lo4.y = tanh_(lo4.y);
                lo4.z = tanh_(lo4.z); lo4.w = tanh_(lo4.w);
                hi4.x = tanh_(hi4.x); hi4.y = tanh_(hi4.y);
                hi4.z = tanh_(hi4.z); hi4.w = tanh_(hi4.w);
                int c0 = n0 + tn * 8 + jj * 4;
                *(float4*)(out + (size_t)r0 * 512 + c0)       = lo4;
                *(float4*)(out + (size_t)(r0 + 1) * 512 + c0) = hi4;
            } else {
                int b  = r0 >> 11;
                int t0 = r0 & 2047;
                int jglob = ((n0 + tn * 8) >> 2) + jj;
                *(float4*)(out + (((size_t)t0 * 512 + jglob) * 32 + b) * 4)       = lo4;
                *(float4*)(out + (((size_t)(t0 + 1) * 512 + jglob) * 32 + b) * 4) = hi4;
            }
        }
    }
}

// ---------------- persistent scan: 4 batch-groups x 32 CTAs, flag dataflow ----------------
// CTA (grp, cix): batches b0=grp*8..+7, hidden cols j0=cix*16..+15, all 4 gates.
// 256 threads, 8 warps; warp w: k in [w*64,+64); lane: b=lane&7, jq=lane>>3.
// SMEM (bytes):
//   w_s  [512k][4jq] uint4x4 {f,i,c,o}, jq stride 80 (bank-staggered), k stride 320
//        : 163840 @ 0
//   h_s  per-warp [64k][8b] f32 : 16384 @ 163840
//   part [8w][128] uint4        : 16384 @ 180224
//   c_s  128 f32                : 512   @ 196608
#define W_OFF     0
#define H_OFF     163840
#define PART_OFF  180224
#define C_OFF     196608
#define SCAN_SMEM 197120

__global__ __launch_bounds__(256, 1) void lstm_scan_kernel(
    const float* __restrict__ Wf, const float* __restrict__ Wi,
    const float* __restrict__ Wc, const float* __restrict__ Wo,
    float* __restrict__ out) {
    extern __shared__ __align__(16) char smraw[];
    uint4* part4 = (uint4*)(smraw + PART_OFF);
    float* c_s   = (float*)(smraw + C_OFF);

    const int tid  = threadIdx.x;
    const int lane = tid & 31;
    const int wrp  = tid >> 5;
    const int grp  = blockIdx.x >> 5;          // 0..3
    const int cix  = blockIdx.x & 31;          // 0..31
    const int j0   = cix * 16;
    const int b0   = grp * 8;

    // fill weight cache: rows 512..1023 of W_*, cols j0..j0+15, staggered layout
    for (int idx = tid; idx < 512 * 16; idx += 256) {
        int j = idx & 15, k = idx >> 4;
        size_t off = (size_t)(512 + k) * HH + (j0 + j);
        uint4 w;
        w.x = __float_as_uint(Wf[off]); w.y = __float_as_uint(Wi[off]);
        w.z = __float_as_uint(Wc[off]); w.w = __float_as_uint(Wo[off]);
        *(uint4*)(smraw + W_OFF + k * 320 + (j >> 2) * 80 + (j & 3) * 16) = w;
    }
    if (tid < 128) c_s[tid] = 0.f;
    __syncthreads();

    const char*     wbase = smraw + W_OFF + (wrp * 64) * 320 + (lane >> 3) * 80;
    const char*     hbase = smraw + H_OFF + wrp * 2048 + (lane & 7) * 4;
    float*          hstg  = (float*)(smraw + H_OFF) + wrp * 512;
    const unsigned* fpoll = g_flags + grp * (CPG * 32) + lane * 32;   // 32 flags, 128B apart
    unsigned*       fmine = g_flags + grp * (CPG * 32) + cix * 32;

    for (int t = 0; t < TT; t++) {
        const unsigned tgt = (unsigned)t;   // need every group flag >= t (h_t published)

        // prefetch this step's input-half pre-activations (independent of h)
        float4 pre4 = make_float4(0.f, 0.f, 0.f, 0.f);
        if (tid < 128) {
            int rj = tid >> 3, rb = tid & 7;
            pre4 = *(const float4*)(g_pre + (((size_t)t * 512 + j0 + rj) * 32 + b0 + rb) * 4);
        }

        // ---- wait: 32 producer flags of this group (1 per lane, acquire) ----
        {
            unsigned v = ldacq(fpoll);
            while (!__all_sync(0xffffffffu, v >= tgt)) v = ldacq(fpoll);
        }

        // ---- load warp's h slice: contiguous 2KB, .cv (L1 bypass) ----
        {
            const float* hg = g_hgrp[t & 1][grp] + wrp * 512;
            #pragma unroll
            for (int i = 0; i < 4; i++) {
                float4 v = ldcv4(hg + (i * 32 + lane) * 4);
                *(float4*)(hstg + (i * 32 + lane) * 4) = v;
            }
        }
        __syncwarp();

        // ---- compute: 64 k-iters; per k: 1 LDS (8-word bcast) + 4 LDS.128 + 8 FFMA2 ----
        unsigned long long afi0 = 0, afi1 = 0, afi2 = 0, afi3 = 0;
        unsigned long long aco0 = 0, aco1 = 0, aco2 = 0, aco3 = 0;
        #pragma unroll 8
        for (int kk = 0; kk < 64; kk++) {
            unsigned long long hv = pack2(*(const float*)(hbase + kk * 32));
            ulonglong2 w0 = *(const ulonglong2*)(wbase + kk * 320);
            ulonglong2 w1 = *(const ulonglong2*)(wbase + kk * 320 + 16);
            ulonglong2 w2 = *(const ulonglong2*)(wbase + kk * 320 + 32);
            ulonglong2 w3 = *(const ulonglong2*)(wbase + kk * 320 + 48);
            afi0 = ffma2(hv, w0.x, afi0); aco0 = ffma2(hv, w0.y, aco0);
            afi1 = ffma2(hv, w1.x, afi1); aco1 = ffma2(hv, w1.y, aco1);
            afi2 = ffma2(hv, w2.x, afi2); aco2 = ffma2(hv, w2.y, aco2);
            afi3 = ffma2(hv, w3.x, aco3 * 0 + afi3); aco3 = ffma2(hv, w3.y, aco3);
        }
        {
            uint4* pp = part4 + wrp * 128 + (lane >> 3) * 32 + (lane & 7);
            float2 a, b2;
            a = unpack2(afi0); b2 = unpack2(aco0);
            pp[0]  = make_uint4(__float_as_uint(a.x), __float_as_uint(a.y),
                                __float_as_uint(b2.x), __float_as_uint(b2.y));
            a = unpack2(afi1); b2 = unpack2(aco1);
            pp[8]  = make_uint4(__float_as_uint(a.x), __float_as_uint(a.y),
                                __float_as_uint(b2.x), __float_as_uint(b2.y));
            a = unpack2(afi2); b2 = unpack2(aco2);
            pp[16] = make_uint4(__float_as_uint(a.x), __float_as_uint(a.y),
                                __float_as_uint(b2.x), __float_as_uint(b2.y));
            a = unpack2(afi3); b2 = unpack2(aco3);
            pp[24] = make_uint4(__float_as_uint(a.x), __float_as_uint(a.y),
                                __float_as_uint(b2.x), __float_as_uint(b2.y));
        }
        __syncthreads();

        if (tid < 128) {
            int rj = tid >> 3, rb = tid & 7;
            float rf = 0.f, ri = 0.f, rc = 0.f, ro = 0.f;
            #pragma unroll
            for (int w = 0; w < 8; w++) {
                uint4 v = part4[w * 128 + tid];
                rf += __uint_as_float(v.x);
                ri += __uint_as_float(v.y);
                rc += __uint_as_float(v.z);
                ro += __uint_as_float(v.w);
            }
            float f  = sig_(pre4.x + rf);
            float ii = sig_(pre4.y + ri);
            float cg = tanh_(pre4.z + rc);
            float o  = sig_(pre4.w + ro);
            float cn = f * c_s[tid] + ii * cg;
            c_s[tid] = cn;
            float h = o * tanh_(cn);
            g_hgrp[(t + 1) & 1][grp][(j0 + rj) * 8 + rb] = h;    // plain store
            __threadfence();   // drain my h store to L2 (release side, R8-proven)
            out[((size_t)(b0 + rb) * TT + t) * HH + j0 + rj] = h;
        }
        __syncthreads();       // all epilogue threads' fences done

        if (tid == 0) {        // publish: my h_{t+1} is visible
            asm volatile("st.release.gpu.u32 [%0], %1;"
                         :: "l"(fmine), "r"((unsigned)(t + 1)) : "memory");
        }
        // no grid barrier; skew bounded to 1 step by the flag protocol
    }
}

extern "C" void kernel_launch(void* const* d_in, const int* in_sizes, int n_in,
                              void* d_out, int out_size) {
    const float* X   = (const float*)d_in[0];
    const float* W_p = (const float*)d_in[1];
    const float* b_p = (const float*)d_in[2];
    const float* W_f = (const float*)d_in[3];
    const float* b_f = (const float*)d_in[4];
    const float* W_i = (const float*)d_in[5];
    const float* b_i = (const float*)d_in[6];
    const float* W_c = (const float*)d_in[7];
    const float* b_c = (const float*)d_in[8];
    const float* W_o = (const float*)d_in[9];
    const float* b_o = (const float*)d_in[10];
    float* out = (float*)d_out;

    cudaFuncSetAttribute(lstm_scan_kernel,
                         cudaFuncAttributeMaxDynamicSharedMemorySize, SCAN_SMEM);

    pack_kernel<<<4096, 256>>>(W_f, W_i, W_c, W_o, b_f, b_i, b_c, b_o);
    gemm_kernel<<<dim3(4, 512), 256>>>(0, X, W_p, b_p);
    gemm_kernel<<<dim3(16, 512), 256>>>(1, nullptr, nullptr, nullptr);
    lstm_scan_kernel<<<NCTA, 256, SCAN_SMEM>>>(W_f, W_i, W_c, W_o, out);
}

// round 15
// speedup vs baseline: 1.5581x; 1.1397x over previous
#include <cuda_runtime.h>
#include <cuda_bf16.h>

#define TT    2048
#define BB    32
#define DD    512
#define HH    512
#define BTR   (BB * TT)          // 65536
#define NCTA  128
#define NGRP  4                  // batch groups (8 batches each)
#define CPG   32                 // CTAs per group (16 j each)

// ---------------- device scratch ----------------
__device__ float g_proj[(size_t)BTR * DD];               // 128 MB
__device__ float g_pre[(size_t)TT * HH * BB * 4];        // 512 MB  [t][j][b][gate]
__device__ float g_wcat[DD * 4 * HH];                    // 4 MB    [k][c], c = j*4+g
__device__ float g_bcat[4 * HH];
// h exchange per group: plain floats [j512][b8], double-buffered
__device__ __align__(16) float g_hgrp[2][NGRP][HH * 8];  // 128 KB
// one flag per producer CTA, 128B-strided: flag = last published generation
__device__ unsigned int g_flags[NGRP * CPG * 32];        // 16 KB

// ---------------- helpers ----------------
__device__ __forceinline__ unsigned long long ffma2(unsigned long long a,
                                                    unsigned long long b,
                                                    unsigned long long c) {
    unsigned long long d;
    asm("fma.rn.f32x2 %0, %1, %2, %3;" : "=l"(d) : "l"(a), "l"(b), "l"(c));
    return d;
}
__device__ __forceinline__ unsigned long long pack2(float x) {
    unsigned long long d;
    asm("mov.b64 %0, {%1, %1};" : "=l"(d) : "f"(x));
    return d;
}
__device__ __forceinline__ float2 unpack2(unsigned long long v) {
    float2 r;
    asm("mov.b64 {%0, %1}, %2;" : "=f"(r.x), "=f"(r.y) : "l"(v));
    return r;
}
__device__ __forceinline__ float4 ldcv4(const float* p) {
    float4 v;
    asm volatile("ld.global.cv.v4.f32 {%0,%1,%2,%3}, [%4];"
                 : "=f"(v.x), "=f"(v.y), "=f"(v.z), "=f"(v.w) : "l"(p));
    return v;
}
__device__ __forceinline__ unsigned ldacq(const unsigned* p) {
    unsigned v;
    asm volatile("ld.acquire.gpu.u32 %0, [%1];" : "=r"(v) : "l"(p) : "memory");
    return v;
}

__device__ __forceinline__ float sig_(float x) {
    return __fdividef(1.f, 1.f + __expf(-x));
}
__device__ __forceinline__ float tanh_(float x) {
    return 1.f - __fdividef(2.f, __expf(2.f * x) + 1.f);
}

// ---------------- pack weights + init state ----------------
__global__ void pack_kernel(const float* __restrict__ Wf, const float* __restrict__ Wi,
                            const float* __restrict__ Wc, const float* __restrict__ Wo,
                            const float* __restrict__ bf, const float* __restrict__ bi,
                            const float* __restrict__ bc, const float* __restrict__ bo) {
    int idx = blockIdx.x * 256 + threadIdx.x;
    if (idx < DD * 4 * HH) {
        int k = idx >> 11;         // input-half row of W_*
        int c = idx & 2047;        // c = j*4+g
        int j = c >> 2, g = c & 3;
        const float* W = (g == 0) ? Wf : (g == 1) ? Wi : (g == 2) ? Wc : Wo;
        g_wcat[idx] = W[(size_t)k * HH + j];
    }
    if (idx < 4 * HH) {
        int j = idx >> 2, g = idx & 3;
        const float* bv = (g == 0) ? bf : (g == 1) ? bi : (g == 2) ? bc : bo;
        g_bcat[idx] = bv[j];
    }
    if (idx < 2 * NGRP * HH * 8) ((float*)g_hgrp)[idx] = 0.f;   // h0 = 0
    if (idx < NGRP * CPG * 32) g_flags[idx] = 0u;               // gen 0 published
}

// ---------------- fp32 SIMT GEMM, f32x2 accumulation (unchanged, proven) ----------------
__global__ __launch_bounds__(256, 2) void gemm_kernel(
    int stage, const float* __restrict__ Aext, const float* __restrict__ Bext,
    const float* __restrict__ biasext) {
    __shared__ __align__(16) float As[16][132];
    __shared__ __align__(16) float Bs[16][128];

    const float* A    = (stage == 0) ? Aext    : g_proj;
    const float* B    = (stage == 0) ? Bext    : g_wcat;
    const float* bias = (stage == 0) ? biasext : g_bcat;
    float* out = (stage == 0) ? g_proj : g_pre;
    const int ldb = (stage == 0) ? 512 : 2048;

    const int tid = threadIdx.x;
    const int m0 = blockIdx.y * 128;
    const int n0 = blockIdx.x * 128;
    const int tm = tid >> 4, tn = tid & 15;

    unsigned long long acc[4][8];
    #pragma unroll
    for (int p = 0; p < 4; p++)
        #pragma unroll
        for (int n = 0; n < 8; n++) acc[p][n] = 0ull;

    for (int k0 = 0; k0 < 512; k0 += 16) {
        #pragma unroll
        for (int i = 0; i < 2; i++) {
            int idx = tid + i * 256;
            int row = idx >> 2, c4 = idx & 3;
            float4 v = *(const float4*)(A + (size_t)(m0 + row) * 512 + k0 + c4 * 4);
            As[c4 * 4 + 0][row] = v.x;
            As[c4 * 4 + 1][row] = v.y;
            As[c4 * 4 + 2][row] = v.z;
            As[c4 * 4 + 3][row] = v.w;
        }
        #pragma unroll
        for (int i = 0; i < 2; i++) {
            int idx = tid + i * 256;
            int row = idx >> 5, c4 = idx & 31;
            *(float4*)&Bs[row][c4 * 4] =
                *(const float4*)(B + (size_t)(k0 + row) * ldb + n0 + c4 * 4);
        }
        __syncthreads();
        #pragma unroll
        for (int kk = 0; kk < 16; kk++) {
            ulonglong2 aA = *(const ulonglong2*)&As[kk][tm * 8];
            ulonglong2 aB = *(const ulonglong2*)&As[kk][tm * 8 + 4];
            float4 b0 = *(const float4*)&Bs[kk][tn * 8];
            float4 b1 = *(const float4*)&Bs[kk][tn * 8 + 4];
            unsigned long long bd[8];
            bd[0] = pack2(b0.x); bd[1] = pack2(b0.y); bd[2] = pack2(b0.z); bd[3] = pack2(b0.w);
            bd[4] = pack2(b1.x); bd[5] = pack2(b1.y); bd[6] = pack2(b1.z); bd[7] = pack2(b1.w);
            #pragma unroll
            for (int n = 0; n < 8; n++) {
                acc[0][n] = ffma2(aA.x, bd[n], acc[0][n]);
                acc[1][n] = ffma2(aA.y, bd[n], acc[1][n]);
                acc[2][n] = ffma2(aB.x, bd[n], acc[2][n]);
                acc[3][n] = ffma2(aB.y, bd[n], acc[3][n]);
            }
        }
        __syncthreads();
    }

    float4 bs0 = *(const float4*)&bias[n0 + tn * 8];
    float4 bs1 = *(const float4*)&bias[n0 + tn * 8 + 4];
    float bv[8] = {bs0.x, bs0.y, bs0.z, bs0.w, bs1.x, bs1.y, bs1.z, bs1.w};

    #pragma unroll
    for (int p = 0; p < 4; p++) {
        int r0 = m0 + tm * 8 + 2 * p;
        #pragma unroll
        for (int jj = 0; jj < 2; jj++) {
            float2 u0 = unpack2(acc[p][jj * 4 + 0]);
            float2 u1 = unpack2(acc[p][jj * 4 + 1]);
            float2 u2 = unpack2(acc[p][jj * 4 + 2]);
            float2 u3 = unpack2(acc[p][jj * 4 + 3]);
            float4 lo4, hi4;
            lo4.x = u0.x + bv[jj * 4 + 0]; hi4.x = u0.y + bv[jj * 4 + 0];
            lo4.y = u1.x + bv[jj * 4 + 1]; hi4.y = u1.y + bv[jj * 4 + 1];
            lo4.z = u2.x + bv[jj * 4 + 2]; hi4.z = u2.y + bv[jj * 4 + 2];
            lo4.w = u3.x + bv[jj * 4 + 3]; hi4.w = u3.y + bv[jj * 4 + 3];
            if (stage == 0) {
                lo4.x = tanh_(lo4.x); lo4.y = tanh_(lo4.y);
                lo4.z = tanh_(lo4.z); lo4.w = tanh_(lo4.w);
                hi4.x = tanh_(hi4.x); hi4.y = tanh_(hi4.y);
                hi4.z = tanh_(hi4.z); hi4.w = tanh_(hi4.w);
                int c0 = n0 + tn * 8 + jj * 4;
                *(float4*)(out + (size_t)r0 * 512 + c0)       = lo4;
                *(float4*)(out + (size_t)(r0 + 1) * 512 + c0) = hi4;
            } else {
                int b  = r0 >> 11;
                int t0 = r0 & 2047;
                int jglob = ((n0 + tn * 8) >> 2) + jj;
                *(float4*)(out + (((size_t)t0 * 512 + jglob) * 32 + b) * 4)       = lo4;
                *(float4*)(out + (((size_t)(t0 + 1) * 512 + jglob) * 32 + b) * 4) = hi4;
            }
        }
    }
}

// ---------------- persistent scan: 4 batch-groups x 32 CTAs, flag dataflow ----------------
// CTA (grp, cix): batches b0=grp*8..+7, hidden cols j0=cix*16..+15, all 4 gates.
// 256 threads, 8 warps; warp w: k in [w*64,+64).
// Lane = (khalf, j): j = lane&15, khalf = lane>>4; iter i handles k = w*64+i*2+khalf.
// Per lane-iter: 1 LDS.128 weights uint4{f,i,c,o}(k,j) + 2 LDS.128 h (8 b as 4 f32x2)
//   -> 16 FFMA2 (4 gates x 4 batch-pairs).
// SMEM (bytes):
//   w_s  [512k][16j] uint4, k-stride 256   : 131072 @ 0
//   h_s  per-warp [64k][8b] f32            : 16384  @ 131072
//   part [16s][16j] 144B (4g x 8b f32 +pad): 36864  @ 147456
//   c_s  128 f32                           : 512    @ 184320
#define W_OFF     0
#define H_OFF     131072
#define PART_OFF  147456
#define C_OFF     184320
#define SCAN_SMEM 184832

__global__ __launch_bounds__(256, 1) void lstm_scan_kernel(
    const float* __restrict__ Wf, const float* __restrict__ Wi,
    const float* __restrict__ Wc, const float* __restrict__ Wo,
    float* __restrict__ out) {
    extern __shared__ __align__(16) char smraw[];
    float* c_s = (float*)(smraw + C_OFF);

    const int tid   = threadIdx.x;
    const int lane  = tid & 31;
    const int wrp   = tid >> 5;
    const int jl    = lane & 15;
    const int khalf = lane >> 4;
    const int grp   = blockIdx.x >> 5;          // 0..3
    const int cix   = blockIdx.x & 31;          // 0..31
    const int j0    = cix * 16;
    const int b0    = grp * 8;

    // fill weight cache: rows 512..1023 of W_*, cols j0..j0+15, [k][j] uint4
    for (int idx = tid; idx < 512 * 16; idx += 256) {
        int k = idx >> 4, j = idx & 15;
        size_t off = (size_t)(512 + k) * HH + (j0 + j);
        uint4 w;
        w.x = __float_as_uint(Wf[off]); w.y = __float_as_uint(Wi[off]);
        w.z = __float_as_uint(Wc[off]); w.w = __float_as_uint(Wo[off]);
        *(uint4*)(smraw + W_OFF + k * 256 + j * 16) = w;
    }
    if (tid < 128) c_s[tid] = 0.f;
    __syncthreads();

    const char*     wb    = smraw + W_OFF + (wrp * 64 + khalf) * 256 + jl * 16;
    const char*     hb    = smraw + H_OFF + wrp * 2048 + khalf * 32;
    float*          hstg  = (float*)(smraw + H_OFF) + wrp * 512;
    char*           ppart = smraw + PART_OFF + ((wrp * 2 + khalf) * 16 + jl) * 144;
    const unsigned* fpoll = g_flags + grp * (CPG * 32) + lane * 32;   // 32 flags, 128B apart
    unsigned*       fmine = g_flags + grp * (CPG * 32) + cix * 32;

    for (int t = 0; t < TT; t++) {
        const unsigned tgt = (unsigned)t;   // need every group flag >= t (h_t published)

        // prefetch this step's input-half pre-activations (independent of h)
        float4 pre4 = make_float4(0.f, 0.f, 0.f, 0.f);
        if (tid < 128) {
            int rj = tid >> 3, rb = tid & 7;
            pre4 = *(const float4*)(g_pre + (((size_t)t * 512 + j0 + rj) * 32 + b0 + rb) * 4);
        }

        // ---- wait: 32 producer flags of this group (1 per lane, acquire) ----
        {
            unsigned v = ldacq(fpoll);
            while (!__all_sync(0xffffffffu, v >= tgt)) v = ldacq(fpoll);
        }

        // ---- load warp's h slice: contiguous 2KB, .cv (L1 bypass), [k][b] ----
        {
            const float* hg = g_hgrp[t & 1][grp] + wrp * 512;
            #pragma unroll
            for (int i = 0; i < 4; i++) {
                float4 v = ldcv4(hg + (i * 32 + lane) * 4);
                *(float4*)(hstg + (i * 32 + lane) * 4) = v;
            }
        }
        __syncwarp();

        // ---- compute: 32 iters x (3 LDS.128 -> 16 FFMA2) ----
        unsigned long long a00 = 0, a01 = 0, a02 = 0, a03 = 0;   // f, bpairs
        unsigned long long a10 = 0, a11 = 0, a12 = 0, a13 = 0;   // i
        unsigned long long a20 = 0, a21 = 0, a22 = 0, a23 = 0;   // c
        unsigned long long a30 = 0, a31 = 0, a32 = 0, a33 = 0;   // o
        #pragma unroll 4
        for (int i = 0; i < 32; i++) {
            uint4 w = *(const uint4*)(wb + i * 512);             // (k, j): f,i,c,o
            ulonglong2 hA = *(const ulonglong2*)(hb + i * 64);       // (b0,b1),(b2,b3)
            ulonglong2 hB = *(const ulonglong2*)(hb + i * 64 + 16);  // (b4,b5),(b6,b7)
            unsigned long long wf = pack2(__uint_as_float(w.x));
            unsigned long long wi = pack2(__uint_as_float(w.y));
            unsigned long long wc = pack2(__uint_as_float(w.z));
            unsigned long long wo = pack2(__uint_as_float(w.w));
            a00 = ffma2(hA.x, wf, a00); a01 = ffma2(hA.y, wf, a01);
            a02 = ffma2(hB.x, wf, a02); a03 = ffma2(hB.y, wf, a03);
            a10 = ffma2(hA.x, wi, a10); a11 = ffma2(hA.y, wi, a11);
            a12 = ffma2(hB.x, wi, a12); a13 = ffma2(hB.y, wi, a13);
            a20 = ffma2(hA.x, wc, a20); a21 = ffma2(hA.y, wc, a21);
            a22 = ffma2(hB.x, wc, a22); a23 = ffma2(hB.y, wc, a23);
            a30 = ffma2(hA.x, wo, a30); a31 = ffma2(hA.y, wo, a31);
            a32 = ffma2(hB.x, wo, a32); a33 = ffma2(hB.y, wo, a33);
        }
        // store partials: [s][j] block of 4 gates x 8 b f32 (b-consecutive)
        {
            ulonglong2 v;
            v.x = a00; v.y = a01; *(ulonglong2*)(ppart +   0) = v;
            v.x = a02; v.y = a03; *(ulonglong2*)(ppart +  16) = v;
            v.x = a10; v.y = a11; *(ulonglong2*)(ppart +  32) = v;
            v.x = a12; v.y = a13; *(ulonglong2*)(ppart +  48) = v;
            v.x = a20; v.y = a21; *(ulonglong2*)(ppart +  64) = v;
            v.x = a22; v.y = a23; *(ulonglong2*)(ppart +  80) = v;
            v.x = a30; v.y = a31; *(ulonglong2*)(ppart +  96) = v;
            v.x = a32; v.y = a33; *(ulonglong2*)(ppart + 112) = v;
        }
        __syncthreads();

        if (tid < 128) {
            int rj = tid >> 3, rb = tid & 7;
            const char* rp = smraw + PART_OFF + rj * 144 + rb * 4;
            float rf = 0.f, ri = 0.f, rc = 0.f, ro = 0.f;
            #pragma unroll
            for (int s = 0; s < 16; s++) {
                const char* q = rp + s * (16 * 144);
                rf += *(const float*)(q +  0);
                ri += *(const float*)(q + 32);
                rc += *(const float*)(q + 64);
                ro += *(const float*)(q + 96);
            }
            float f  = sig_(pre4.x + rf);
            float ii = sig_(pre4.y + ri);
            float cg = tanh_(pre4.z + rc);
            float o  = sig_(pre4.w + ro);
            float cn = f * c_s[tid] + ii * cg;
            c_s[tid] = cn;
            float h = o * tanh_(cn);
            g_hgrp[(t + 1) & 1][grp][(j0 + rj) * 8 + rb] = h;    // plain store
            __threadfence();   // drain my h store to L2 (release side)
            out[((size_t)(b0 + rb) * TT + t) * HH + j0 + rj] = h;
        }
        __syncthreads();       // all epilogue threads' fences done

        if (tid == 0) {        // publish: my h_{t+1} is visible
            asm volatile("st.release.gpu.u32 [%0], %1;"
                         :: "l"(fmine), "r"((unsigned)(t + 1)) : "memory");
        }
        // no grid barrier; skew bounded to 1 step by the flag protocol
    }
}

extern "C" void kernel_launch(void* const* d_in, const int* in_sizes, int n_in,
                              void* d_out, int out_size) {
    const float* X   = (const float*)d_in[0];
    const float* W_p = (const float*)d_in[1];
    const float* b_p = (const float*)d_in[2];
    const float* W_f = (const float*)d_in[3];
    const float* b_f = (const float*)d_in[4];
    const float* W_i = (const float*)d_in[5];
    const float* b_i = (const float*)d_in[6];
    const float* W_c = (const float*)d_in[7];
    const float* b_c = (const float*)d_in[8];
    const float* W_o = (const float*)d_in[9];
    const float* b_o = (const float*)d_in[10];
    float* out = (float*)d_out;

    cudaFuncSetAttribute(lstm_scan_kernel,
                         cudaFuncAttributeMaxDynamicSharedMemorySize, SCAN_SMEM);

    pack_kernel<<<4096, 256>>>(W_f, W_i, W_c, W_o, b_f, b_i, b_c, b_o);
    gemm_kernel<<<dim3(4, 512), 256>>>(0, X, W_p, b_p);
    gemm_kernel<<<dim3(16, 512), 256>>>(1, nullptr, nullptr, nullptr);
    lstm_scan_kernel<<<NCTA, 256, SCAN_SMEM>>>(W_f, W_i, W_c, W_o, out);
}

// round 16
// speedup vs baseline: 1.6175x; 1.0381x over previous
#include <cuda_runtime.h>
#include <cuda_bf16.h>

#define TT    2048
#define BB    32
#define DD    512
#define HH    512
#define BTR   (BB * TT)          // 65536
#define NCTA  128
#define NGRP  4                  // batch groups (8 batches each)
#define CPG   32                 // CTAs per group (16 j each)

// ---------------- device scratch ----------------
__device__ float g_proj[(size_t)BTR * DD];               // 128 MB
__device__ float g_pre[(size_t)TT * HH * BB * 4];        // 512 MB  [t][j][b][gate]
__device__ float g_wcat[DD * 4 * HH];                    // 4 MB    [k][c], c = j*4+g
__device__ float g_bcat[4 * HH];
// h exchange per group: plain floats [j512][b8], double-buffered
__device__ __align__(16) float g_hgrp[2][NGRP][HH * 8];  // 128 KB
// one flag per producer CTA, 128B-strided: flag = last published generation
__device__ unsigned int g_flags[NGRP * CPG * 32];        // 16 KB

// ---------------- helpers ----------------
__device__ __forceinline__ unsigned long long ffma2(unsigned long long a,
                                                    unsigned long long b,
                                                    unsigned long long c) {
    unsigned long long d;
    asm("fma.rn.f32x2 %0, %1, %2, %3;" : "=l"(d) : "l"(a), "l"(b), "l"(c));
    return d;
}
__device__ __forceinline__ unsigned long long pack2(float x) {
    unsigned long long d;
    asm("mov.b64 %0, {%1, %1};" : "=l"(d) : "f"(x));
    return d;
}
__device__ __forceinline__ float2 unpack2(unsigned long long v) {
    float2 r;
    asm("mov.b64 {%0, %1}, %2;" : "=f"(r.x), "=f"(r.y) : "l"(v));
    return r;
}
__device__ __forceinline__ float4 ldcv4(const float* p) {
    float4 v;
    asm volatile("ld.global.cv.v4.f32 {%0,%1,%2,%3}, [%4];"
                 : "=f"(v.x), "=f"(v.y), "=f"(v.z), "=f"(v.w) : "l"(p));
    return v;
}
__device__ __forceinline__ unsigned ldacq(const unsigned* p) {
    unsigned v;
    asm volatile("ld.acquire.gpu.u32 %0, [%1];" : "=r"(v) : "l"(p) : "memory");
    return v;
}

__device__ __forceinline__ float sig_(float x) {
    return __fdividef(1.f, 1.f + __expf(-x));
}
__device__ __forceinline__ float tanh_(float x) {
    return 1.f - __fdividef(2.f, __expf(2.f * x) + 1.f);
}

// ---------------- pack weights + init state ----------------
__global__ void pack_kernel(const float* __restrict__ Wf, const float* __restrict__ Wi,
                            const float* __restrict__ Wc, const float* __restrict__ Wo,
                            const float* __restrict__ bf, const float* __restrict__ bi,
                            const float* __restrict__ bc, const float* __restrict__ bo) {
    int idx = blockIdx.x * 256 + threadIdx.x;
    if (idx < DD * 4 * HH) {
        int k = idx >> 11;         // input-half row of W_*
        int c = idx & 2047;        // c = j*4+g
        int j = c >> 2, g = c & 3;
        const float* W = (g == 0) ? Wf : (g == 1) ? Wi : (g == 2) ? Wc : Wo;
        g_wcat[idx] = W[(size_t)k * HH + j];
    }
    if (idx < 4 * HH) {
        int j = idx >> 2, g = idx & 3;
        const float* bv = (g == 0) ? bf : (g == 1) ? bi : (g == 2) ? bc : bo;
        g_bcat[idx] = bv[j];
    }
    if (idx < 2 * NGRP * HH * 8) ((float*)g_hgrp)[idx] = 0.f;   // h0 = 0
    if (idx < NGRP * CPG * 32) g_flags[idx] = 0u;               // gen 0 published
}

// ---------------- fp32 SIMT GEMM, f32x2 accumulation (unchanged, proven) ----------------
__global__ __launch_bounds__(256, 2) void gemm_kernel(
    int stage, const float* __restrict__ Aext, const float* __restrict__ Bext,
    const float* __restrict__ biasext) {
    __shared__ __align__(16) float As[16][132];
    __shared__ __align__(16) float Bs[16][128];

    const float* A    = (stage == 0) ? Aext    : g_proj;
    const float* B    = (stage == 0) ? Bext    : g_wcat;
    const float* bias = (stage == 0) ? biasext : g_bcat;
    float* out = (stage == 0) ? g_proj : g_pre;
    const int ldb = (stage == 0) ? 512 : 2048;

    const int tid = threadIdx.x;
    const int m0 = blockIdx.y * 128;
    const int n0 = blockIdx.x * 128;
    const int tm = tid >> 4, tn = tid & 15;

    unsigned long long acc[4][8];
    #pragma unroll
    for (int p = 0; p < 4; p++)
        #pragma unroll
        for (int n = 0; n < 8; n++) acc[p][n] = 0ull;

    for (int k0 = 0; k0 < 512; k0 += 16) {
        #pragma unroll
        for (int i = 0; i < 2; i++) {
            int idx = tid + i * 256;
            int row = idx >> 2, c4 = idx & 3;
            float4 v = *(const float4*)(A + (size_t)(m0 + row) * 512 + k0 + c4 * 4);
            As[c4 * 4 + 0][row] = v.x;
            As[c4 * 4 + 1][row] = v.y;
            As[c4 * 4 + 2][row] = v.z;
            As[c4 * 4 + 3][row] = v.w;
        }
        #pragma unroll
        for (int i = 0; i < 2; i++) {
            int idx = tid + i * 256;
            int row = idx >> 5, c4 = idx & 31;
            *(float4*)&Bs[row][c4 * 4] =
                *(const float4*)(B + (size_t)(k0 + row) * ldb + n0 + c4 * 4);
        }
        __syncthreads();
        #pragma unroll
        for (int kk = 0; kk < 16; kk++) {
            ulonglong2 aA = *(const ulonglong2*)&As[kk][tm * 8];
            ulonglong2 aB = *(const ulonglong2*)&As[kk][tm * 8 + 4];
            float4 b0 = *(const float4*)&Bs[kk][tn * 8];
            float4 b1 = *(const float4*)&Bs[kk][tn * 8 + 4];
            unsigned long long bd[8];
            bd[0] = pack2(b0.x); bd[1] = pack2(b0.y); bd[2] = pack2(b0.z); bd[3] = pack2(b0.w);
            bd[4] = pack2(b1.x); bd[5] = pack2(b1.y); bd[6] = pack2(b1.z); bd[7] = pack2(b1.w);
            #pragma unroll
            for (int n = 0; n < 8; n++) {
                acc[0][n] = ffma2(aA.x, bd[n], acc[0][n]);
                acc[1][n] = ffma2(aA.y, bd[n], acc[1][n]);
                acc[2][n] = ffma2(aB.x, bd[n], acc[2][n]);
                acc[3][n] = ffma2(aB.y, bd[n], acc[3][n]);
            }
        }
        __syncthreads();
    }

    float4 bs0 = *(const float4*)&bias[n0 + tn * 8];
    float4 bs1 = *(const float4*)&bias[n0 + tn * 8 + 4];
    float bv[8] = {bs0.x, bs0.y, bs0.z, bs0.w, bs1.x, bs1.y, bs1.z, bs1.w};

    #pragma unroll
    for (int p = 0; p < 4; p++) {
        int r0 = m0 + tm * 8 + 2 * p;
        #pragma unroll
        for (int jj = 0; jj < 2; jj++) {
            float2 u0 = unpack2(acc[p][jj * 4 + 0]);
            float2 u1 = unpack2(acc[p][jj * 4 + 1]);
            float2 u2 = unpack2(acc[p][jj * 4 + 2]);
            float2 u3 = unpack2(acc[p][jj * 4 + 3]);
            float4 lo4, hi4;
            lo4.x = u0.x + bv[jj * 4 + 0]; hi4.x = u0.y + bv[jj * 4 + 0];
            lo4.y = u1.x + bv[jj * 4 + 1]; hi4.y = u1.y + bv[jj * 4 + 1];
            lo4.z = u2.x + bv[jj * 4 + 2]; hi4.z = u2.y + bv[jj * 4 + 2];
            lo4.w = u3.x + bv[jj * 4 + 3]; hi4.w = u3.y + bv[jj * 4 + 3];
            if (stage == 0) {
                lo4.x = tanh_(lo4.x); lo4.y = tanh_(lo4.y);
                lo4.z = tanh_(lo4.z); lo4.w = tanh_(lo4.w);
                hi4.x = tanh_(hi4.x); hi4.y = tanh_(hi4.y);
                hi4.z = tanh_(hi4.z); hi4.w = tanh_(hi4.w);
                int c0 = n0 + tn * 8 + jj * 4;
                *(float4*)(out + (size_t)r0 * 512 + c0)       = lo4;
                *(float4*)(out + (size_t)(r0 + 1) * 512 + c0) = hi4;
            } else {
                int b  = r0 >> 11;
                int t0 = r0 & 2047;
                int jglob = ((n0 + tn * 8) >> 2) + jj;
                *(float4*)(out + (((size_t)t0 * 512 + jglob) * 32 + b) * 4)       = lo4;
                *(float4*)(out + (((size_t)(t0 + 1) * 512 + jglob) * 32 + b) * 4) = hi4;
            }
        }
    }
}

// ---------------- persistent scan: register weights + pipelined epilogue ----------------
// CTA (grp, cix): batches b0=grp*8..+7, hidden cols j0=cix*16..+15, all 4 gates.
// 256 threads, 8 warps; warp w: k in [w*64,+64).
// Lane = (khalf, jl): jl = lane&15, khalf = lane>>4; iter i handles k = w*64+i*2+khalf.
// Weights live in 128 REGISTERS per thread (uint4 wreg[32] = {f,i,c,o} per k-iter).
// Per iter: 2 LDS.128 h + 4 pack + 16 FFMA2 (4 gates x 4 batch-pairs).
// Warps 0-3: compute + epilogue (bar.sync 1). Warps 4-7: compute only (bar.arrive 1),
// pipeline into step t+1 during epilogue t. Partials double-buffered.
// SMEM (bytes):
//   w_s  [512k][16j] uint4 (staging only)   : 131072 @ 0
//   h_s  per-warp [64k][8b] f32             : 16384  @ 131072
//   part [2][16s][16j] 144B (4g x 8b f32)   : 73728  @ 147456
//   c_s  128 f32                            : 512    @ 221184
#define W_OFF     0
#define H_OFF     131072
#define PART_OFF  147456
#define C_OFF     221184
#define SCAN_SMEM 221696

__global__ __launch_bounds__(256, 1) void lstm_scan_kernel(
    const float* __restrict__ Wf, const float* __restrict__ Wi,
    const float* __restrict__ Wc, const float* __restrict__ Wo,
    float* __restrict__ out) {
    extern __shared__ __align__(16) char smraw[];
    float* c_s = (float*)(smraw + C_OFF);

    const int tid   = threadIdx.x;
    const int lane  = tid & 31;
    const int wrp   = tid >> 5;
    const int jl    = lane & 15;
    const int khalf = lane >> 4;
    const int grp   = blockIdx.x >> 5;          // 0..3
    const int cix   = blockIdx.x & 31;          // 0..31
    const int j0    = cix * 16;
    const int b0    = grp * 8;

    // stage weights into smem (coalesced), then pull my 32 uint4 into registers
    for (int idx = tid; idx < 512 * 16; idx += 256) {
        int k = idx >> 4, j = idx & 15;
        size_t off = (size_t)(512 + k) * HH + (j0 + j);
        uint4 w;
        w.x = __float_as_uint(Wf[off]); w.y = __float_as_uint(Wi[off]);
        w.z = __float_as_uint(Wc[off]); w.w = __float_as_uint(Wo[off]);
        *(uint4*)(smraw + W_OFF + k * 256 + j * 16) = w;
    }
    if (tid < 128) c_s[tid] = 0.f;
    __syncthreads();

    uint4 wreg[32];
    {
        const char* wb = smraw + W_OFF + (wrp * 64 + khalf) * 256 + jl * 16;
        #pragma unroll
        for (int i = 0; i < 32; i++) wreg[i] = *(const uint4*)(wb + i * 512);
    }

    const char*     hb    = smraw + H_OFF + wrp * 2048 + khalf * 32;
    float*          hstg  = (float*)(smraw + H_OFF) + wrp * 512;
    const unsigned* fpoll = g_flags + grp * (CPG * 32) + lane * 32;   // 32 flags, 128B apart
    unsigned*       fmine = g_flags + grp * (CPG * 32) + cix * 32;

    for (int t = 0; t < TT; t++) {
        const unsigned tgt = (unsigned)t;   // need every group flag >= t (h_t published)
        const int pbuf = t & 1;

        // prefetch this step's input-half pre-activations (independent of h)
        float4 pre4 = make_float4(0.f, 0.f, 0.f, 0.f);
        if (tid < 128) {
            int rj = tid >> 3, rb = tid & 7;
            pre4 = *(const float4*)(g_pre + (((size_t)t * 512 + j0 + rj) * 32 + b0 + rb) * 4);
        }

        // ---- wait: 32 producer flags of this group (1 per lane, acquire) ----
        {
            unsigned v = ldacq(fpoll);
            while (!__all_sync(0xffffffffu, v >= tgt)) v = ldacq(fpoll);
        }

        // ---- load warp's h slice: contiguous 2KB, .cv (L1 bypass), [k][b] ----
        {
            const float* hg = g_hgrp[t & 1][grp] + wrp * 512;
            #pragma unroll
            for (int i = 0; i < 4; i++) {
                float4 v = ldcv4(hg + (i * 32 + lane) * 4);
                *(float4*)(hstg + (i * 32 + lane) * 4) = v;
            }
        }
        __syncwarp();

        // ---- compute: 32 iters x (2 LDS.128 h + reg weights -> 16 FFMA2) ----
        unsigned long long a00 = 0, a01 = 0, a02 = 0, a03 = 0;   // f, bpairs
        unsigned long long a10 = 0, a11 = 0, a12 = 0, a13 = 0;   // i
        unsigned long long a20 = 0, a21 = 0, a22 = 0, a23 = 0;   // c
        unsigned long long a30 = 0, a31 = 0, a32 = 0, a33 = 0;   // o
        #pragma unroll
        for (int i = 0; i < 32; i++) {
            ulonglong2 hA = *(const ulonglong2*)(hb + i * 64);       // (b0,b1),(b2,b3)
            ulonglong2 hB = *(const ulonglong2*)(hb + i * 64 + 16);  // (b4,b5),(b6,b7)
            uint4 w = wreg[i];
            unsigned long long wf = pack2(__uint_as_float(w.x));
            unsigned long long wi = pack2(__uint_as_float(w.y));
            unsigned long long wc = pack2(__uint_as_float(w.z));
            unsigned long long wo = pack2(__uint_as_float(w.w));
            a00 = ffma2(hA.x, wf, a00); a01 = ffma2(hA.y, wf, a01);
            a02 = ffma2(hB.x, wf, a02); a03 = ffma2(hB.y, wf, a03);
            a10 = ffma2(hA.x, wi, a10); a11 = ffma2(hA.y, wi, a11);
            a12 = ffma2(hB.x, wi, a12); a13 = ffma2(hB.y, wi, a13);
            a20 = ffma2(hA.x, wc, a20); a21 = ffma2(hA.y, wc, a21);
            a22 = ffma2(hB.x, wc, a22); a23 = ffma2(hB.y, wc, a23);
            a30 = ffma2(hA.x, wo, a30); a31 = ffma2(hA.y, wo, a31);
            a32 = ffma2(hB.x, wo, a32); a33 = ffma2(hB.y, wo, a33);
        }
        // store partials into buffer pbuf: [s][j] block of 4g x 8b f32
        {
            char* ppart = smraw + PART_OFF + pbuf * 36864
                        + ((wrp * 2 + khalf) * 16 + jl) * 144;
            ulonglong2 v;
            v.x = a00; v.y = a01; *(ulonglong2*)(ppart +   0) = v;
            v.x = a02; v.y = a03; *(ulonglong2*)(ppart +  16) = v;
            v.x = a10; v.y = a11; *(ulonglong2*)(ppart +  32) = v;
            v.x = a12; v.y = a13; *(ulonglong2*)(ppart +  48) = v;
            v.x = a20; v.y = a21; *(ulonglong2*)(ppart +  64) = v;
            v.x = a22; v.y = a23; *(ulonglong2*)(ppart +  80) = v;
            v.x = a30; v.y = a31; *(ulonglong2*)(ppart +  96) = v;
            v.x = a32; v.y = a33; *(ulonglong2*)(ppart + 112) = v;
        }

        if (wrp >= 4) {
            // producers: signal partials ready, pipeline straight into step t+1
            asm volatile("bar.arrive 1, 256;" ::: "memory");
            continue;
        }

        // consumers (warps 0-3): wait for all partials of step t
        asm volatile("bar.sync 1, 256;" ::: "memory");

        {
            int rj = tid >> 3, rb = tid & 7;
            const char* rp = smraw + PART_OFF + pbuf * 36864 + rj * 144 + rb * 4;
            float rf = 0.f, ri = 0.f, rc = 0.f, ro = 0.f;
            #pragma unroll
            for (int s = 0; s < 16; s++) {
                const char* q = rp + s * (16 * 144);
                rf += *(const float*)(q +  0);
                ri += *(const float*)(q + 32);
                rc += *(const float*)(q + 64);
                ro += *(const float*)(q + 96);
            }
            float f  = sig_(pre4.x + rf);
            float ii = sig_(pre4.y + ri);
            float cg = tanh_(pre4.z + rc);
            float o  = sig_(pre4.w + ro);
            float cn = f * c_s[tid] + ii * cg;
            c_s[tid] = cn;
            float h = o * tanh_(cn);
            g_hgrp[(t + 1) & 1][grp][(j0 + rj) * 8 + rb] = h;    // plain store
            out[((size_t)(b0 + rb) * TT + t) * HH + j0 + rj] = h;
        }
        // epilogue-only barrier (cumulative CTA fence), then single release store
        asm volatile("bar.sync 2, 128;" ::: "memory");
        if (tid == 0) {
            asm volatile("st.release.gpu.u32 [%0], %1;"
                         :: "l"(fmine), "r"((unsigned)(t + 1)) : "memory");
        }
    }
}

extern "C" void kernel_launch(void* const* d_in, const int* in_sizes, int n_in,
                              void* d_out, int out_size) {
    const float* X   = (const float*)d_in[0];
    const float* W_p = (const float*)d_in[1];
    const float* b_p = (const float*)d_in[2];
    const float* W_f = (const float*)d_in[3];
    const float* b_f = (const float*)d_in[4];
    const float* W_i = (const float*)d_in[5];
    const float* b_i = (const float*)d_in[6];
    const float* W_c = (const float*)d_in[7];
    const float* b_c = (const float*)d_in[8];
    const float* W_o = (const float*)d_in[9];
    const float* b_o = (const float*)d_in[10];
    float* out = (float*)d_out;

    cudaFuncSetAttribute(lstm_scan_kernel,
                         cudaFuncAttributeMaxDynamicSharedMemorySize, SCAN_SMEM);

    pack_kernel<<<4096, 256>>>(W_f, W_i, W_c, W_o, b_f, b_i, b_c, b_o);
    gemm_kernel<<<dim3(4, 512), 256>>>(0, X, W_p, b_p);
    gemm_kernel<<<dim3(16, 512), 256>>>(1, nullptr, nullptr, nullptr);
    lstm_scan_kernel<<<NCTA, 256, SCAN_SMEM>>>(W_f, W_i, W_c, W_o, out);
}